// round 1
// baseline (speedup 1.0000x reference)
#include <cuda_runtime.h>

typedef unsigned long long u64;

#define NP 64
#define NCOLS 500000
#define PAIRS (NCOLS / 2)      /* 250000 f32x2 column-pairs */
#define NANG 2016

// RT[r*64 + i] = mus[i] * R[i][r]  (R = product of Givens rotations)
__device__ float d_RT[NP * NP];

// ---------------------------------------------------------------------------
// Kernel 1: build the 64x64 combined rotation+scale matrix.
// 64 threads, thread j owns column j of M (no cross-thread deps -> no syncs
// inside the rotation loop). The iTop row value is carried in a register
// across the inner iBtm loop to shorten the dependency chain.
// ---------------------------------------------------------------------------
__global__ void build_R_kernel(const float* __restrict__ angles,
                               const float* __restrict__ mus) {
    __shared__ float  Msm[NP * NP];
    __shared__ float2 cs[NANG];
    const int j = threadIdx.x;

    for (int k = j; k < NANG; k += NP) {
        float s, c;
        sincosf(angles[k], &s, &c);
        cs[k] = make_float2(c, s);
    }
    #pragma unroll
    for (int i = 0; i < NP; i++) Msm[i * NP + j] = (i == j) ? 1.0f : 0.0f;
    __syncthreads();

    int k = 0;
    for (int it = 0; it < NP - 1; it++) {
        float vt = Msm[it * NP + j];
        for (int ib = it + 1; ib < NP; ib++, k++) {
            float2 c_s = cs[k];
            float  mb  = Msm[ib * NP + j];
            float  nvt = c_s.x * vt - c_s.y * mb;      // vt' = c*vt - s*vb
            Msm[ib * NP + j] = c_s.y * vt + c_s.x * mb; // vb' = s*vt + c*vb
            vt = nvt;
        }
        Msm[it * NP + j] = vt;
    }
    // thread j holds column j of R -> writes row j of RT (RT[r][i] = M[i][r]*mus[i])
    for (int i = 0; i < NP; i++)
        d_RT[j * NP + i] = Msm[i * NP + j] * mus[i];
}

// ---------------------------------------------------------------------------
// Kernel 2: Y = M @ X with packed f32x2 FMAs (FFMA2, 2x fp32 throughput).
// Each thread: 2 adjacent columns (one f32x2 lane-pair), 64 accumulators.
// R is broadcast from smem, pre-duplicated as (v,v) u64 so no per-FMA packing.
// X is streamed with a 4-row prefetch pipeline.
// ---------------------------------------------------------------------------
__device__ __forceinline__ void fma2(u64& d, u64 a, u64 b) {
    asm("fma.rn.f32x2 %0, %1, %2, %0;" : "+l"(d) : "l"(a), "l"(b));
}
__device__ __forceinline__ u64 dup2(float v) {
    u64 r;
    asm("mov.b64 %0, {%1, %1};" : "=l"(r) : "r"(__float_as_uint(v)));
    return r;
}

__global__ void __launch_bounds__(256, 1)
gemm_kernel(const float* __restrict__ X, float* __restrict__ out) {
    __shared__ __align__(16) u64 sR[NP * NP];  // duplicated (v,v) pairs, 32 KB

    const int tid = threadIdx.x;
    const float4* R4 = (const float4*)d_RT;
    for (int t = tid; t < NP * NP / 4; t += 256) {
        float4 v = R4[t];
        sR[t * 4 + 0] = dup2(v.x);
        sR[t * 4 + 1] = dup2(v.y);
        sR[t * 4 + 2] = dup2(v.z);
        sR[t * 4 + 3] = dup2(v.w);
    }
    __syncthreads();

    const int  p      = blockIdx.x * 256 + tid;
    const bool active = (p < PAIRS);
    const int  pc     = active ? p : (PAIRS - 1);  // clamp so prefetches stay in-bounds

    const u64* Xu = (const u64*)X;
    u64*       Ou = (u64*)out;

    u64 acc[NP];
    #pragma unroll
    for (int i = 0; i < NP; i++) acc[i] = 0ULL;

    u64 xv[4];
    #pragma unroll
    for (int kk = 0; kk < 4; kk++) xv[kk] = Xu[kk * PAIRS + pc];

    #pragma unroll 1
    for (int r0 = 0; r0 < NP; r0 += 4) {
        u64 cur[4];
        #pragma unroll
        for (int kk = 0; kk < 4; kk++) cur[kk] = xv[kk];
        if (r0 + 4 < NP) {
            #pragma unroll
            for (int kk = 0; kk < 4; kk++)
                xv[kk] = Xu[(r0 + 4 + kk) * PAIRS + pc];
        }
        #pragma unroll
        for (int kk = 0; kk < 4; kk++) {
            const int r = r0 + kk;
            const ulonglong2* sR2 = (const ulonglong2*)&sR[r * NP];
            #pragma unroll
            for (int ii = 0; ii < NP / 2; ii++) {
                ulonglong2 rv = sR2[ii];           // LDS.128 broadcast: 2 dup'd R values
                fma2(acc[2 * ii + 0], rv.x, cur[kk]);
                fma2(acc[2 * ii + 1], rv.y, cur[kk]);
            }
        }
    }

    if (active) {
        #pragma unroll
        for (int i = 0; i < NP; i++) Ou[i * PAIRS + p] = acc[i];
    }
}

// ---------------------------------------------------------------------------
extern "C" void kernel_launch(void* const* d_in, const int* in_sizes, int n_in,
                              void* d_out, int out_size) {
    const float* X      = (const float*)d_in[0];
    const float* angles = (const float*)d_in[1];
    const float* mus    = (const float*)d_in[2];
    float*       out    = (float*)d_out;

    build_R_kernel<<<1, NP>>>(angles, mus);
    const int grid = (PAIRS + 255) / 256;
    gemm_kernel<<<grid, 256>>>(X, out);
}